// round 1
// baseline (speedup 1.0000x reference)
#include <cuda_runtime.h>
#include <math.h>

#define NQ 4096
#define NC 1024
#define DD 513
#define DP 528           // padded K (multiple of 16)
#define NITER 20
#define EPS8 1e-8f

// ---------------- persistent device buffers ----------------
__device__ float g_qhat  [NQ * DP];     // [q0, -q_space], zero padded
__device__ float g_protos[NC * DP];     // [time, space...], zero padded
__device__ float g_logits[NQ * NC];     // logits, later overwritten by W
__device__ float g_factor[NQ * NC];     // dlogit/dz = -2a/sqrt(z^2-1)
__device__ float g_P     [NQ * NC];
__device__ float g_cm    [NC];
__device__ float g_colpart[32 * NC];
__device__ float g_grad  [NC * DP];
__device__ float g_m     [NC * DP];
__device__ float g_v     [NC * DP];

// ---------------- prep ----------------
__global__ void prep_q_kernel(const float* __restrict__ q) {
    int idx = blockIdx.x * blockDim.x + threadIdx.x;
    if (idx >= NQ * DP) return;
    int i = idx / DP, d = idx % DP;
    float v = 0.0f;
    if (d < DD) { v = q[i * DD + d]; if (d > 0) v = -v; }
    g_qhat[idx] = v;
}

__global__ void prep_p_kernel(const float* __restrict__ p) {
    int idx = blockIdx.x * blockDim.x + threadIdx.x;
    if (idx >= NC * DP) return;
    int i = idx / DP, d = idx % DP;
    float v = 0.0f;
    if (d < DD) v = p[i * DD + d];
    g_protos[idx] = v;
    g_m[idx] = 0.0f;
    g_v[idx] = 0.0f;
}

// ---------------- GEMM1: NI = qhat @ protos^T, fused acosh epilogue ----------------
// C[4096,1024], K = 528. 64x64 tiles, 256 threads, 4x4 per thread.
__global__ __launch_bounds__(256) void gemm1_kernel() {
    __shared__ float As[16][68];
    __shared__ float Bs[16][68];

    const int tid = threadIdx.x;
    const int tx = tid % 16;           // n sub-tile
    const int ty = tid / 16;           // m sub-tile
    const int n0 = blockIdx.x * 64;    // over NC
    const int m0 = blockIdx.y * 64;    // over NQ

    float acc[4][4];
#pragma unroll
    for (int r = 0; r < 4; r++)
#pragma unroll
        for (int c = 0; c < 4; c++) acc[r][c] = 0.0f;

    const int lk = tid % 16;
    const int lm = tid / 16;

    for (int kk = 0; kk < DP; kk += 16) {
#pragma unroll
        for (int r = 0; r < 4; r++) {
            As[lk][lm + 16 * r] = g_qhat  [(m0 + lm + 16 * r) * DP + kk + lk];
            Bs[lk][lm + 16 * r] = g_protos[(n0 + lm + 16 * r) * DP + kk + lk];
        }
        __syncthreads();
#pragma unroll
        for (int k = 0; k < 16; k++) {
            float4 a4 = *(const float4*)&As[k][ty * 4];
            float4 b4 = *(const float4*)&Bs[k][tx * 4];
            float a[4] = {a4.x, a4.y, a4.z, a4.w};
            float b[4] = {b4.x, b4.y, b4.z, b4.w};
#pragma unroll
            for (int r = 0; r < 4; r++)
#pragma unroll
                for (int c = 0; c < 4; c++) acc[r][c] = fmaf(a[r], b[c], acc[r][c]);
        }
        __syncthreads();
    }

    const float CL = 1.0f + 1e-7f;
#pragma unroll
    for (int r = 0; r < 4; r++) {
#pragma unroll
        for (int c = 0; c < 4; c++) {
            int gi = m0 + ty * 4 + r;
            int gj = n0 + tx * 4 + c;
            float niv = acc[r][c];
            float z = fmaxf(niv, CL);
            float w = fmaf(z, z, -1.0f);
            float rs = rsqrtf(w);
            float a = __logf(fmaf(w, rs, z));      // log(z + sqrt(z^2-1))
            g_logits[gi * NC + gj] = -a * a;
            g_factor[gi * NC + gj] = (niv > CL) ? (-2.0f * a * rs) : 0.0f;
        }
    }
}

// ---------------- row softmax ----------------
__global__ __launch_bounds__(256) void softmax_kernel() {
    __shared__ float red[256];
    const int i = blockIdx.x;
    const int t = threadIdx.x;
    const float* L = g_logits + i * NC;

    float l[4];
    float mx = -1e30f;
#pragma unroll
    for (int e = 0; e < 4; e++) { l[e] = L[t + 256 * e]; mx = fmaxf(mx, l[e]); }
    red[t] = mx; __syncthreads();
    for (int s = 128; s > 0; s >>= 1) { if (t < s) red[t] = fmaxf(red[t], red[t + s]); __syncthreads(); }
    mx = red[0]; __syncthreads();

    float ex[4];
    float sm = 0.0f;
#pragma unroll
    for (int e = 0; e < 4; e++) { ex[e] = __expf(l[e] - mx); sm += ex[e]; }
    red[t] = sm; __syncthreads();
    for (int s = 128; s > 0; s >>= 1) { if (t < s) red[t] += red[t + s]; __syncthreads(); }
    float inv = 1.0f / red[0];

    float* P = g_P + i * NC;
#pragma unroll
    for (int e = 0; e < 4; e++) P[t + 256 * e] = ex[e] * inv;
}

// ---------------- column partial sums of P ----------------
__global__ __launch_bounds__(256) void colpart_kernel() {
    const int j = blockIdx.x * 256 + threadIdx.x;
    const int i0 = blockIdx.y * 128;
    float s = 0.0f;
    for (int i = i0; i < i0 + 128; i++) s += g_P[i * NC + j];
    g_colpart[blockIdx.y * NC + j] = s;
}

__global__ __launch_bounds__(256) void colreduce_kernel() {
    const int j = blockIdx.x * 256 + threadIdx.x;
    float s = 0.0f;
#pragma unroll
    for (int r = 0; r < 32; r++) s += g_colpart[r * NC + j];
    float pm = s * (1.0f / NQ);
    g_cm[j] = __logf(pm + EPS8) + pm / (pm + EPS8);
}

// ---------------- W = dL/d(neg_inner), overwrites g_logits ----------------
__global__ __launch_bounds__(256) void gradw_kernel() {
    __shared__ float red[256];
    const int i = blockIdx.x;
    const int t = threadIdx.x;
    const int base = i * NC;

    float p[4], gg[4];
    float sl = 0.0f;
#pragma unroll
    for (int e = 0; e < 4; e++) {
        int j = t + 256 * e;
        float pv = g_P[base + j];
        float gv = (g_cm[j] - __logf(pv + EPS8) - pv / (pv + EPS8)) * (1.0f / NQ);
        p[e] = pv; gg[e] = gv;
        sl += pv * gv;
    }
    red[t] = sl; __syncthreads();
    for (int s = 128; s > 0; s >>= 1) { if (t < s) red[t] += red[t + s]; __syncthreads(); }
    float S = red[0];

#pragma unroll
    for (int e = 0; e < 4; e++) {
        int j = t + 256 * e;
        g_logits[base + j] = p[e] * (gg[e] - S) * g_factor[base + j];
    }
}

// ---------------- GEMM2: grad = W^T @ qhat  (C[1024, 528], K=4096) ----------------
__global__ __launch_bounds__(256) void gemm2_kernel() {
    __shared__ float Ws[16][68];
    __shared__ float Qs[16][68];

    const int tid = threadIdx.x;
    const int tx = tid % 16;            // n (d) sub-tile
    const int ty = tid / 16;            // m (j) sub-tile
    const int n0 = blockIdx.x * 64;     // over DP (9 tiles, last partial)
    const int m0 = blockIdx.y * 64;     // over NC

    float acc[4][4];
#pragma unroll
    for (int r = 0; r < 4; r++)
#pragma unroll
        for (int c = 0; c < 4; c++) acc[r][c] = 0.0f;

    const int lm = tid % 64;
    const int lk = tid / 64;            // 0..3

    for (int kk = 0; kk < NQ; kk += 16) {
#pragma unroll
        for (int r = 0; r < 4; r++) {
            int k = lk + 4 * r;
            Ws[k][lm] = g_logits[(kk + k) * NC + m0 + lm];  // W
            int d = n0 + lm;
            Qs[k][lm] = (d < DP) ? g_qhat[(kk + k) * DP + d] : 0.0f;
        }
        __syncthreads();
#pragma unroll
        for (int k = 0; k < 16; k++) {
            float4 a4 = *(const float4*)&Ws[k][ty * 4];
            float4 b4 = *(const float4*)&Qs[k][tx * 4];
            float a[4] = {a4.x, a4.y, a4.z, a4.w};
            float b[4] = {b4.x, b4.y, b4.z, b4.w};
#pragma unroll
            for (int r = 0; r < 4; r++)
#pragma unroll
                for (int c = 0; c < 4; c++) acc[r][c] = fmaf(a[r], b[c], acc[r][c]);
        }
        __syncthreads();
    }

#pragma unroll
    for (int r = 0; r < 4; r++) {
#pragma unroll
        for (int c = 0; c < 4; c++) {
            int gj = m0 + ty * 4 + r;
            int gd = n0 + tx * 4 + c;
            if (gd < DP) g_grad[gj * DP + gd] = acc[r][c];
        }
    }
}

// ---------------- AdamW + reproject ----------------
__global__ __launch_bounds__(256) void adam_kernel(float corr1, float corr2) {
    __shared__ float red[256];
    const int j = blockIdx.x;
    const int t = threadIdx.x;

    float ss = 0.0f;
#pragma unroll
    for (int e = 0; e < 2; e++) {
        int d = 1 + t + 256 * e;      // space coords 1..512
        int idx = j * DP + d;
        float g = g_grad[idx];
        float m = 0.9f  * g_m[idx] + 0.1f  * g;
        float v = 0.999f * g_v[idx] + 0.001f * (g * g);
        g_m[idx] = m; g_v[idx] = v;
        float mh = m * corr1;
        float vh = v * corr2;
        float x = g_protos[idx] * 0.999f - 0.1f * mh / (sqrtf(vh) + EPS8);
        g_protos[idx] = x;
        ss += x * x;
    }
    red[t] = ss; __syncthreads();
    for (int s = 128; s > 0; s >>= 1) { if (t < s) red[t] += red[t + s]; __syncthreads(); }
    if (t == 0) g_protos[j * DP] = sqrtf(1.0f + red[0]);
}

// ---------------- pack output ----------------
__global__ void pack_kernel(float* __restrict__ out) {
    int idx = blockIdx.x * blockDim.x + threadIdx.x;
    if (idx >= NC * DD) return;
    int i = idx / DD, d = idx % DD;
    out[idx] = g_protos[i * DP + d];
}

// ---------------- launch ----------------
extern "C" void kernel_launch(void* const* d_in, const int* in_sizes, int n_in,
                              void* d_out, int out_size) {
    const float* protos_in = (const float*)d_in[0];
    const float* query_in  = (const float*)d_in[1];
    (void)in_sizes; (void)n_in;

    prep_q_kernel<<<(NQ * DP + 255) / 256, 256>>>(query_in);
    prep_p_kernel<<<(NC * DP + 255) / 256, 256>>>(protos_in);

    for (int t = 1; t <= NITER; t++) {
        gemm1_kernel<<<dim3(NC / 64, NQ / 64), 256>>>();
        softmax_kernel<<<NQ, 256>>>();
        colpart_kernel<<<dim3(NC / 256, 32), 256>>>();
        colreduce_kernel<<<NC / 256, 256>>>();
        gradw_kernel<<<NQ, 256>>>();
        gemm2_kernel<<<dim3((DP + 63) / 64, NC / 64), 256>>>();
        double c1 = 1.0 / (1.0 - pow(0.9,   (double)t));
        double c2 = 1.0 / (1.0 - pow(0.999, (double)t));
        adam_kernel<<<NC, 256>>>((float)c1, (float)c2);
    }
    pack_kernel<<<(NC * DD + 255) / 256, 256>>>((float*)d_out);
}

// round 3
// speedup vs baseline: 2.3900x; 2.3900x over previous
#include <cuda_runtime.h>
#include <cuda_bf16.h>
#include <math.h>
#include <stdint.h>

#define NQ 4096
#define NC 1024
#define DD 513
#define DP 528            // fp32 padded dim
#define K1 1600           // 3*528 = 1584 -> pad to 1600 (25*64)
#define K2 (3*NQ)         // 12288
#define DPAD2 640         // gemm2 N padded (5*128)
#define NITER 20
#define EPS8 1e-8f

__device__ __forceinline__ uint32_t smem_u32(const void* p) {
    uint32_t a;
    asm("{ .reg .u64 t; cvta.to.shared.u64 t, %1; cvt.u32.u64 %0, t; }" : "=r"(a) : "l"(p));
    return a;
}

// ================= persistent buffers =================
__device__ float g_qhat  [NQ * DP];
__device__ float g_protos[NC * DP];
__device__ float g_logits[NQ * NC];      // logits, later fp32 W
__device__ float g_factor[NQ * NC];
__device__ float g_P     [NQ * NC];
__device__ float g_cm    [NC];
__device__ float g_colpart[32 * NC];
__device__ float g_m     [NC * DP];
__device__ float g_v     [NC * DP];
__device__ __nv_bfloat16 g_q3 [(size_t)NQ * K1];        // [qh|qh|ql]
__device__ __nv_bfloat16 g_p3 [(size_t)NC * K1];        // [ph|pl|ph]
__device__ __nv_bfloat16 g_qT3[(size_t)DPAD2 * K2];     // [qh^T|ql^T|qh^T]
__device__ __nv_bfloat16 g_Wt3[(size_t)NC * K2];        // [Wh^T|Wh^T|Wl^T]
__device__ float g_gpart[4 * (size_t)NC * DPAD2];

__device__ __forceinline__ void split2(float v, __nv_bfloat16& hi, __nv_bfloat16& lo) {
    hi = __float2bfloat16(v);
    lo = __float2bfloat16(v - __bfloat162float(hi));
}

// ================= prep =================
__global__ void prep_q_kernel(const float* __restrict__ q) {
    int idx = blockIdx.x * blockDim.x + threadIdx.x;
    if (idx >= NQ * DP) return;
    int i = idx / DP, d = idx % DP;
    float v = 0.0f;
    if (d < DD) { v = q[i * DD + d]; if (d > 0) v = -v; }
    g_qhat[idx] = v;
}
__global__ void prep_q3_kernel() {
    int idx = blockIdx.x * blockDim.x + threadIdx.x;
    if (idx >= NQ * K1) return;
    int i = idx / K1, d = idx % K1;
    __nv_bfloat16 out = __float2bfloat16(0.0f);
    if (d < 1584) {
        int sec = d / 528, dd = d % 528;
        float v = g_qhat[i * DP + dd];
        __nv_bfloat16 hi, lo; split2(v, hi, lo);
        out = (sec == 2) ? lo : hi;
    }
    g_q3[(size_t)i * K1 + d] = out;
}
__global__ void prep_qT3_kernel() {
    int idx = blockIdx.x * blockDim.x + threadIdx.x;
    if (idx >= DPAD2 * NQ) return;
    int d = idx / NQ, i = idx % NQ;
    float v = (d < DP) ? g_qhat[i * DP + d] : 0.0f;
    __nv_bfloat16 hi, lo; split2(v, hi, lo);
    size_t base = (size_t)d * K2 + i;
    g_qT3[base] = hi; g_qT3[base + NQ] = lo; g_qT3[base + 2 * NQ] = hi;
}
__global__ void prep_p_kernel(const float* __restrict__ p) {
    int idx = blockIdx.x * blockDim.x + threadIdx.x;
    if (idx >= NC * DP) return;
    int i = idx / DP, d = idx % DP;
    float v = 0.0f;
    if (d < DD) v = p[i * DD + d];
    g_protos[idx] = v;
    g_m[idx] = 0.0f;
    g_v[idx] = 0.0f;
}
__global__ void split_p_kernel() {
    int idx = blockIdx.x * blockDim.x + threadIdx.x;
    if (idx >= NC * K1) return;
    int j = idx / K1, d = idx % K1;
    __nv_bfloat16 out = __float2bfloat16(0.0f);
    if (d < 1584) {
        int sec = d / 528, dd = d % 528;
        float v = g_protos[j * DP + dd];
        __nv_bfloat16 hi, lo; split2(v, hi, lo);
        out = (sec == 1) ? lo : hi;
    }
    g_p3[(size_t)j * K1 + d] = out;
}

// ================= mma.sync GEMM =================
// C = A[M,K] @ B[N,K]^T, bf16 K-major, fp32 accum.
// CTA tile 128x128, K-step 64, cp.async double buffer, 8 warps (4M x 2N).
// MODE 1: logits = q3 @ p3^T with acosh epilogue.    grid (8, 32)
// MODE 2: grad partials = Wt3 @ qT3^T, split-K=4.    grid (5, 8, 4)
#define SMEM_BYTES 65536

__device__ __forceinline__ void ld_x4(uint32_t* r, uint32_t addr) {
    asm volatile("ldmatrix.sync.aligned.m8n8.x4.shared.b16 {%0,%1,%2,%3}, [%4];"
        : "=r"(r[0]), "=r"(r[1]), "=r"(r[2]), "=r"(r[3]) : "r"(addr));
}
__device__ __forceinline__ void mma16816(float* d, const uint32_t* a, const uint32_t* b) {
    asm volatile("mma.sync.aligned.m16n8k16.row.col.f32.bf16.bf16.f32 "
        "{%0,%1,%2,%3}, {%4,%5,%6,%7}, {%8,%9}, {%0,%1,%2,%3};"
        : "+f"(d[0]), "+f"(d[1]), "+f"(d[2]), "+f"(d[3])
        : "r"(a[0]), "r"(a[1]), "r"(a[2]), "r"(a[3]), "r"(b[0]), "r"(b[1]));
}

__device__ __forceinline__ void load_stage(uint32_t sA, const char* Ab, const char* Bb,
                                           size_t kbytes, size_t gk, int tid) {
    uint32_t sB = sA + 16384;
#pragma unroll
    for (int t = 0; t < 4; t++) {
        int idx = tid + 256 * t;
        int r = idx >> 3, c = idx & 7;
        uint32_t sw = (uint32_t)(r * 128 + ((c ^ (r & 7)) << 4));
        const char* g = Ab + (size_t)r * kbytes + gk + c * 16;
        asm volatile("cp.async.cg.shared.global [%0], [%1], 16;" :: "r"(sA + sw), "l"(g));
    }
#pragma unroll
    for (int t = 0; t < 4; t++) {
        int idx = tid + 256 * t;
        int r = idx >> 3, c = idx & 7;
        uint32_t sw = (uint32_t)(r * 128 + ((c ^ (r & 7)) << 4));
        const char* g = Bb + (size_t)r * kbytes + gk + c * 16;
        asm volatile("cp.async.cg.shared.global [%0], [%1], 16;" :: "r"(sB + sw), "l"(g));
    }
    asm volatile("cp.async.commit_group;" ::: "memory");
}

template <int MODE>
__global__ __launch_bounds__(256) void mma_gemm() {
    extern __shared__ char smem[];
    const uint32_t sb = smem_u32(smem);
    const int tid = threadIdx.x;
    const int warp = tid >> 5, lane = tid & 31;
    const int wm = warp & 3, wn = warp >> 2;

    const int m0 = blockIdx.y * 128;
    const int n0 = blockIdx.x * 128;
    const char* Abase;
    const char* Bbase;
    size_t kbytes, koff;
    int nch;
    if (MODE == 1) {
        Abase = (const char*)g_q3 + (size_t)m0 * K1 * 2;
        Bbase = (const char*)g_p3 + (size_t)n0 * K1 * 2;
        kbytes = (size_t)K1 * 2; nch = K1 / 64; koff = 0;
    } else {
        Abase = (const char*)g_Wt3 + (size_t)m0 * K2 * 2;
        Bbase = (const char*)g_qT3 + (size_t)n0 * K2 * 2;
        kbytes = (size_t)K2 * 2; nch = (K2 / 4) / 64;
        koff = (size_t)blockIdx.z * (size_t)(K2 / 4) * 2;
    }

    load_stage(sb, Abase, Bbase, kbytes, koff, tid);
    load_stage(sb + 32768, Abase, Bbase, kbytes, koff + 128, tid);
    asm volatile("cp.async.wait_group 1;" ::: "memory");
    __syncthreads();

    float acc[2][8][4];
#pragma unroll
    for (int mt = 0; mt < 2; mt++)
#pragma unroll
        for (int nt = 0; nt < 8; nt++)
#pragma unroll
            for (int e = 0; e < 4; e++) acc[mt][nt][e] = 0.0f;

    for (int ch = 0; ch < nch; ch++) {
        const int st = ch & 1;
        const uint32_t sA = sb + st * 32768;
        const uint32_t sB = sA + 16384;

#pragma unroll
        for (int kk = 0; kk < 4; kk++) {
            uint32_t a[2][4], b[8][2];
#pragma unroll
            for (int mt = 0; mt < 2; mt++) {
                int r = wm * 32 + mt * 16 + (lane & 15);
                int c = ((lane >> 4) + 2 * kk) ^ (r & 7);
                ld_x4(a[mt], sA + r * 128 + c * 16);
            }
#pragma unroll
            for (int np = 0; np < 4; np++) {
                int r = wn * 64 + np * 16 + (lane & 7) + ((lane >> 4) << 3);
                int c = (((lane >> 3) & 1) + 2 * kk) ^ (r & 7);
                uint32_t tmp[4];
                ld_x4(tmp, sB + r * 128 + c * 16);
                b[2 * np][0] = tmp[0]; b[2 * np][1] = tmp[1];
                b[2 * np + 1][0] = tmp[2]; b[2 * np + 1][1] = tmp[3];
            }
#pragma unroll
            for (int mt = 0; mt < 2; mt++)
#pragma unroll
                for (int nt = 0; nt < 8; nt++)
                    mma16816(acc[mt][nt], a[mt], b[nt]);
        }

        if (ch + 1 < nch) {
            if (ch + 2 < nch) {
                __syncthreads();  // all warps done reading buf st before overwrite
                load_stage(sb + st * 32768, Abase, Bbase, kbytes, koff + (size_t)(ch + 2) * 128, tid);
                asm volatile("cp.async.wait_group 1;" ::: "memory");
            } else {
                asm volatile("cp.async.wait_group 0;" ::: "memory");
            }
            __syncthreads();
        }
    }

    // ---------------- epilogue (register fragments -> gmem) ----------------
    const float CL = 1.0f + 1e-7f;
#pragma unroll
    for (int mt = 0; mt < 2; mt++) {
#pragma unroll
        for (int nt = 0; nt < 8; nt++) {
            int col = n0 + wn * 64 + nt * 8 + (lane & 3) * 2;
#pragma unroll
            for (int h = 0; h < 2; h++) {
                int row = m0 + wm * 32 + mt * 16 + (lane >> 2) + 8 * h;
                float v0 = acc[mt][nt][2 * h + 0];
                float v1 = acc[mt][nt][2 * h + 1];
                if (MODE == 1) {
                    float2 lg, fc;
                    {
                        float z = fmaxf(v0, CL);
                        float w = fmaf(z, z, -1.0f);
                        float rs = rsqrtf(w);
                        float aa = __logf(fmaf(w, rs, z));
                        lg.x = -aa * aa;
                        fc.x = (v0 > CL) ? (-2.0f * aa * rs) : 0.0f;
                    }
                    {
                        float z = fmaxf(v1, CL);
                        float w = fmaf(z, z, -1.0f);
                        float rs = rsqrtf(w);
                        float aa = __logf(fmaf(w, rs, z));
                        lg.y = -aa * aa;
                        fc.y = (v1 > CL) ? (-2.0f * aa * rs) : 0.0f;
                    }
                    *(float2*)&g_logits[(size_t)row * NC + col] = lg;
                    *(float2*)&g_factor[(size_t)row * NC + col] = fc;
                } else {
                    float* out = g_gpart + (size_t)blockIdx.z * NC * DPAD2;
                    float2 gv; gv.x = v0; gv.y = v1;
                    *(float2*)&out[(size_t)row * DPAD2 + col] = gv;
                }
            }
        }
    }
}

// ================= elementwise chain =================
__global__ __launch_bounds__(256) void softmax_kernel() {
    __shared__ float red[256];
    const int i = blockIdx.x;
    const int t = threadIdx.x;
    const float* L = g_logits + (size_t)i * NC;

    float l[4];
    float mx = -1e30f;
#pragma unroll
    for (int e = 0; e < 4; e++) { l[e] = L[t + 256 * e]; mx = fmaxf(mx, l[e]); }
    red[t] = mx; __syncthreads();
    for (int sft = 128; sft > 0; sft >>= 1) { if (t < sft) red[t] = fmaxf(red[t], red[t + sft]); __syncthreads(); }
    mx = red[0]; __syncthreads();

    float ex[4];
    float sm = 0.0f;
#pragma unroll
    for (int e = 0; e < 4; e++) { ex[e] = __expf(l[e] - mx); sm += ex[e]; }
    red[t] = sm; __syncthreads();
    for (int sft = 128; sft > 0; sft >>= 1) { if (t < sft) red[t] += red[t + sft]; __syncthreads(); }
    float inv = 1.0f / red[0];

    float* P = g_P + (size_t)i * NC;
#pragma unroll
    for (int e = 0; e < 4; e++) P[t + 256 * e] = ex[e] * inv;
}

__global__ __launch_bounds__(256) void colpart_kernel() {
    const int j = blockIdx.x * 256 + threadIdx.x;
    const int i0 = blockIdx.y * 128;
    float sacc = 0.0f;
    for (int i = i0; i < i0 + 128; i++) sacc += g_P[(size_t)i * NC + j];
    g_colpart[blockIdx.y * NC + j] = sacc;
}

__global__ __launch_bounds__(256) void colreduce_kernel() {
    const int j = blockIdx.x * 256 + threadIdx.x;
    float sacc = 0.0f;
#pragma unroll
    for (int r = 0; r < 32; r++) sacc += g_colpart[r * NC + j];
    float pm = sacc * (1.0f / NQ);
    g_cm[j] = __logf(pm + EPS8) + pm / (pm + EPS8);
}

__global__ __launch_bounds__(256) void gradw_kernel() {
    __shared__ float red[256];
    const int i = blockIdx.x;
    const int t = threadIdx.x;
    const size_t base = (size_t)i * NC;

    float p[4], gg[4];
    float sl = 0.0f;
#pragma unroll
    for (int e = 0; e < 4; e++) {
        int j = t + 256 * e;
        float pv = g_P[base + j];
        float gv = (g_cm[j] - __logf(pv + EPS8) - pv / (pv + EPS8)) * (1.0f / NQ);
        p[e] = pv; gg[e] = gv;
        sl += pv * gv;
    }
    red[t] = sl; __syncthreads();
    for (int sft = 128; sft > 0; sft >>= 1) { if (t < sft) red[t] += red[t + sft]; __syncthreads(); }
    float S = red[0];

#pragma unroll
    for (int e = 0; e < 4; e++) {
        int j = t + 256 * e;
        g_logits[base + j] = p[e] * (gg[e] - S) * g_factor[base + j];
    }
}

// W (fp32, [i][j]) -> transposed bf16 split: g_Wt3[j][ Wh(i) | Wh(i) | Wl(i) ]
__global__ __launch_bounds__(256) void wsplit_kernel() {
    __shared__ float s[32][33];
    const int i0 = blockIdx.x * 32;   // over NQ
    const int j0 = blockIdx.y * 32;   // over NC
    const int t = threadIdx.x;
    const int x = t & 31, y = t >> 5;
#pragma unroll
    for (int r = 0; r < 4; r++)
        s[y + 8 * r][x] = g_logits[(size_t)(i0 + y + 8 * r) * NC + j0 + x];
    __syncthreads();
#pragma unroll
    for (int w = t; w < 512; w += 256) {
        int j = w >> 4, ip = w & 15;
        float v0 = s[2 * ip][j], v1 = s[2 * ip + 1][j];
        __nv_bfloat16 h0, l0, h1, l1;
        split2(v0, h0, l0); split2(v1, h1, l1);
        __nv_bfloat162 hh; hh.x = h0; hh.y = h1;
        __nv_bfloat162 ll; ll.x = l0; ll.y = l1;
        size_t base = (size_t)(j0 + j) * K2 + i0 + 2 * ip;
        *(__nv_bfloat162*)&g_Wt3[base] = hh;
        *(__nv_bfloat162*)&g_Wt3[base + NQ] = hh;
        *(__nv_bfloat162*)&g_Wt3[base + 2 * NQ] = ll;
    }
}

// ================= AdamW + reproject =================
__global__ __launch_bounds__(256) void adam_kernel(float corr1, float corr2) {
    __shared__ float red[256];
    const int j = blockIdx.x;
    const int t = threadIdx.x;

    float ss = 0.0f;
#pragma unroll
    for (int e = 0; e < 2; e++) {
        int d = 1 + t + 256 * e;
        int idx = j * DP + d;
        float g = 0.0f;
#pragma unroll
        for (int sp = 0; sp < 4; sp++)
            g += g_gpart[(size_t)sp * NC * DPAD2 + (size_t)j * DPAD2 + d];
        float m = 0.9f * g_m[idx] + 0.1f * g;
        float v = 0.999f * g_v[idx] + 0.001f * (g * g);
        g_m[idx] = m; g_v[idx] = v;
        float mh = m * corr1;
        float vh = v * corr2;
        float x = g_protos[idx] * 0.999f - 0.1f * mh / (sqrtf(vh) + EPS8);
        g_protos[idx] = x;
        ss += x * x;
    }
    red[t] = ss; __syncthreads();
    for (int sft = 128; sft > 0; sft >>= 1) { if (t < sft) red[t] += red[t + sft]; __syncthreads(); }
    if (t == 0) g_protos[j * DP] = sqrtf(1.0f + red[0]);
}

__global__ void pack_kernel(float* __restrict__ out) {
    int idx = blockIdx.x * blockDim.x + threadIdx.x;
    if (idx >= NC * DD) return;
    int i = idx / DD, d = idx % DD;
    out[idx] = g_protos[i * DP + d];
}

// ================= launch =================
extern "C" void kernel_launch(void* const* d_in, const int* in_sizes, int n_in,
                              void* d_out, int out_size) {
    const float* protos_in = (const float*)d_in[0];
    const float* query_in  = (const float*)d_in[1];
    (void)in_sizes; (void)n_in; (void)out_size;

    cudaFuncSetAttribute(mma_gemm<1>, cudaFuncAttributeMaxDynamicSharedMemorySize, SMEM_BYTES);
    cudaFuncSetAttribute(mma_gemm<2>, cudaFuncAttributeMaxDynamicSharedMemorySize, SMEM_BYTES);

    prep_q_kernel<<<(NQ * DP + 255) / 256, 256>>>(query_in);
    prep_q3_kernel<<<(NQ * K1 + 255) / 256, 256>>>();
    prep_qT3_kernel<<<(DPAD2 * NQ + 255) / 256, 256>>>();
    prep_p_kernel<<<(NC * DP + 255) / 256, 256>>>(protos_in);

    for (int t = 1; t <= NITER; t++) {
        split_p_kernel<<<(NC * K1 + 255) / 256, 256>>>();
        mma_gemm<1><<<dim3(NC / 128, NQ / 128), 256, SMEM_BYTES>>>();
        softmax_kernel<<<NQ, 256>>>();
        colpart_kernel<<<dim3(NC / 256, 32), 256>>>();
        colreduce_kernel<<<NC / 256, 256>>>();
        gradw_kernel<<<NQ, 256>>>();
        wsplit_kernel<<<dim3(NQ / 32, NC / 32), 256>>>();
        mma_gemm<2><<<dim3(DPAD2 / 128, NC / 128, 4), 256, SMEM_BYTES>>>();
        double c1 = 1.0 / (1.0 - pow(0.9,   (double)t));
        double c2 = 1.0 / (1.0 - pow(0.999, (double)t));
        adam_kernel<<<NC, 256>>>((float)c1, (float)c2);
    }
    pack_kernel<<<(NC * DD + 255) / 256, 256>>>((float*)d_out);
}

// round 4
// speedup vs baseline: 2.5636x; 1.0726x over previous
#include <cuda_runtime.h>
#include <cuda_bf16.h>
#include <math.h>
#include <stdint.h>

#define NQ 4096
#define NC 1024
#define DD 513
#define DP 528            // fp32 padded dim
#define K1 2112           // 4 sections * 528
#define NDIM2 512         // gemm2 N (space coords 1..512)
#define KSEC 4096         // gemm2 per-section K
#define NITER 20
#define EPS8 1e-8f
#define INVN (1.0f/4096.0f)

__device__ __forceinline__ uint32_t smem_u32(const void* p) {
    uint32_t a;
    asm("{ .reg .u64 t; cvta.to.shared.u64 t, %1; cvt.u32.u64 %0, t; }" : "=r"(a) : "l"(p));
    return a;
}

// ================= persistent buffers =================
__device__ float g_qhat  [NQ * DP];
__device__ float g_protos[NC * DP];
__device__ float g_logits[NQ * NC];
__device__ float g_factor[NQ * NC];
__device__ float g_P     [NQ * NC];
__device__ float g_cm    [NC];
__device__ float g_Arow  [NQ];           // -dot/N per row
__device__ float g_colpart[32 * NC];
__device__ float g_m     [NC * DP];
__device__ float g_v     [NC * DP];
__device__ __nv_bfloat16 g_q4 [(size_t)NQ * K1];          // [qh|qh|ql|ql]
__device__ __nv_bfloat16 g_p4 [(size_t)NC * K1];          // [ph|pl|ph|pl]
__device__ __nv_bfloat16 g_qT2[2][(size_t)NDIM2 * KSEC];  // [qh^T], [ql^T]
__device__ __nv_bfloat16 g_Wt2[2][(size_t)NC * KSEC];     // [Wh^T], [Wl^T]
__device__ float g_gpart[6 * (size_t)NC * NDIM2];

__device__ __forceinline__ void split2(float v, __nv_bfloat16& hi, __nv_bfloat16& lo) {
    hi = __float2bfloat16(v);
    lo = __float2bfloat16(v - __bfloat162float(hi));
}

// ================= prep =================
__global__ void prep_q_kernel(const float* __restrict__ q) {
    int idx = blockIdx.x * blockDim.x + threadIdx.x;
    if (idx >= NQ * DP) return;
    int i = idx / DP, d = idx % DP;
    float v = 0.0f;
    if (d < DD) { v = q[i * DD + d]; if (d > 0) v = -v; }
    g_qhat[idx] = v;
}
__global__ void prep_q4_kernel() {
    int idx = blockIdx.x * blockDim.x + threadIdx.x;
    if (idx >= NQ * K1) return;
    int i = idx / K1, d = idx % K1;
    int sec = d / DP, dd = d % DP;
    float v = g_qhat[i * DP + dd];
    __nv_bfloat16 hi, lo; split2(v, hi, lo);
    g_q4[(size_t)i * K1 + d] = (sec < 2) ? hi : lo;
}
__global__ void prep_qT2_kernel() {
    int idx = blockIdx.x * blockDim.x + threadIdx.x;
    if (idx >= NDIM2 * NQ) return;
    int r = idx / NQ, i = idx % NQ;
    float v = g_qhat[i * DP + r + 1];
    __nv_bfloat16 hi, lo; split2(v, hi, lo);
    g_qT2[0][(size_t)r * KSEC + i] = hi;
    g_qT2[1][(size_t)r * KSEC + i] = lo;
}
__global__ void prep_p_kernel(const float* __restrict__ p) {
    int idx = blockIdx.x * blockDim.x + threadIdx.x;
    if (idx >= NC * DP) return;
    int i = idx / DP, d = idx % DP;
    float v = 0.0f;
    if (d < DD) v = p[i * DD + d];
    g_protos[idx] = v;
    g_m[idx] = 0.0f;
    g_v[idx] = 0.0f;
}
__global__ void split_p_kernel() {
    int idx = blockIdx.x * blockDim.x + threadIdx.x;
    if (idx >= NC * K1) return;
    int j = idx / K1, d = idx % K1;
    int sec = d / DP, dd = d % DP;
    float v = g_protos[j * DP + dd];
    __nv_bfloat16 hi, lo; split2(v, hi, lo);
    g_p4[(size_t)j * K1 + d] = (sec & 1) ? lo : hi;
}

// ================= mma.sync GEMM (3-stage cp.async pipeline) =================
// MODE 1: logits = q4 @ p4^T + acosh epilogue.  grid (8, 32). K=2112 (33 chunks)
// MODE 2: grad partials, 3 section-pairs x split-2.  grid (4, 8, 6). K=2048/CTA
#define SMEM_BYTES 98304

__device__ __forceinline__ void ld_x4(uint32_t* r, uint32_t addr) {
    asm volatile("ldmatrix.sync.aligned.m8n8.x4.shared.b16 {%0,%1,%2,%3}, [%4];"
        : "=r"(r[0]), "=r"(r[1]), "=r"(r[2]), "=r"(r[3]) : "r"(addr));
}
__device__ __forceinline__ void mma16816(float* d, const uint32_t* a, const uint32_t* b) {
    asm volatile("mma.sync.aligned.m16n8k16.row.col.f32.bf16.bf16.f32 "
        "{%0,%1,%2,%3}, {%4,%5,%6,%7}, {%8,%9}, {%0,%1,%2,%3};"
        : "+f"(d[0]), "+f"(d[1]), "+f"(d[2]), "+f"(d[3])
        : "r"(a[0]), "r"(a[1]), "r"(a[2]), "r"(a[3]), "r"(b[0]), "r"(b[1]));
}

__device__ __forceinline__ void load_stage(uint32_t sA, const char* Ab, const char* Bb,
                                           size_t kbytes, size_t gk, int tid) {
    uint32_t sB = sA + 16384;
#pragma unroll
    for (int t = 0; t < 4; t++) {
        int idx = tid + 256 * t;
        int r = idx >> 3, c = idx & 7;
        uint32_t sw = (uint32_t)(r * 128 + ((c ^ (r & 7)) << 4));
        const char* g = Ab + (size_t)r * kbytes + gk + c * 16;
        asm volatile("cp.async.cg.shared.global [%0], [%1], 16;" :: "r"(sA + sw), "l"(g));
    }
#pragma unroll
    for (int t = 0; t < 4; t++) {
        int idx = tid + 256 * t;
        int r = idx >> 3, c = idx & 7;
        uint32_t sw = (uint32_t)(r * 128 + ((c ^ (r & 7)) << 4));
        const char* g = Bb + (size_t)r * kbytes + gk + c * 16;
        asm volatile("cp.async.cg.shared.global [%0], [%1], 16;" :: "r"(sB + sw), "l"(g));
    }
    asm volatile("cp.async.commit_group;" ::: "memory");
}

template <int MODE>
__global__ __launch_bounds__(256) void mma_gemm() {
    extern __shared__ char smem[];
    const uint32_t sb = smem_u32(smem);
    const int tid = threadIdx.x;
    const int warp = tid >> 5, lane = tid & 31;
    const int wm = warp & 3, wn = warp >> 2;

    const int m0 = blockIdx.y * 128;
    const int n0 = blockIdx.x * 128;
    const char* Abase;
    const char* Bbase;
    size_t kbytes, koff;
    int nch;
    if (MODE == 1) {
        Abase = (const char*)g_q4 + (size_t)m0 * K1 * 2;
        Bbase = (const char*)g_p4 + (size_t)n0 * K1 * 2;
        kbytes = (size_t)K1 * 2; nch = K1 / 64; koff = 0;
    } else {
        int z = blockIdx.z;
        int s = z >> 1, h = z & 1;
        int ai = (s == 2) ? 1 : 0;
        int bi = (s == 1) ? 1 : 0;
        Abase = (const char*)&g_Wt2[ai][0] + (size_t)m0 * KSEC * 2;
        Bbase = (const char*)&g_qT2[bi][0] + (size_t)n0 * KSEC * 2;
        kbytes = (size_t)KSEC * 2; nch = 2048 / 64;
        koff = (size_t)h * 2048 * 2;
    }

    // prologue: 2 stages in flight
    load_stage(sb, Abase, Bbase, kbytes, koff, tid);
    load_stage(sb + 32768, Abase, Bbase, kbytes, koff + 128, tid);
    asm volatile("cp.async.wait_group 1;" ::: "memory");
    __syncthreads();

    float acc[2][8][4];
#pragma unroll
    for (int mt = 0; mt < 2; mt++)
#pragma unroll
        for (int nt = 0; nt < 8; nt++)
#pragma unroll
            for (int e = 0; e < 4; e++) acc[mt][nt][e] = 0.0f;

    for (int ch = 0; ch < nch; ch++) {
        const uint32_t sA = sb + (uint32_t)(ch % 3) * 32768;
        const uint32_t sB = sA + 16384;

#pragma unroll
        for (int kk = 0; kk < 4; kk++) {
            uint32_t a[2][4], b[8][2];
#pragma unroll
            for (int mt = 0; mt < 2; mt++) {
                int r = wm * 32 + mt * 16 + (lane & 15);
                int c = ((lane >> 4) + 2 * kk) ^ (r & 7);
                ld_x4(a[mt], sA + r * 128 + c * 16);
            }
#pragma unroll
            for (int np = 0; np < 4; np++) {
                int r = wn * 64 + np * 16 + (lane & 7) + ((lane >> 4) << 3);
                int c = (((lane >> 3) & 1) + 2 * kk) ^ (r & 7);
                uint32_t tmp[4];
                ld_x4(tmp, sB + r * 128 + c * 16);
                b[2 * np][0] = tmp[0]; b[2 * np][1] = tmp[1];
                b[2 * np + 1][0] = tmp[2]; b[2 * np + 1][1] = tmp[3];
            }
#pragma unroll
            for (int mt = 0; mt < 2; mt++)
#pragma unroll
                for (int nt = 0; nt < 8; nt++)
                    mma16816(acc[mt][nt], a[mt], b[nt]);
        }

        if (ch + 2 < nch) {
            load_stage(sb + (uint32_t)((ch + 2) % 3) * 32768, Abase, Bbase,
                       kbytes, koff + (size_t)(ch + 2) * 128, tid);
            asm volatile("cp.async.wait_group 1;" ::: "memory");
        } else {
            asm volatile("cp.async.wait_group 0;" ::: "memory");
        }
        __syncthreads();
    }

    // ---------------- epilogue ----------------
    const float CL = 1.0f + 1e-7f;
#pragma unroll
    for (int mt = 0; mt < 2; mt++) {
#pragma unroll
        for (int nt = 0; nt < 8; nt++) {
            int col = n0 + wn * 64 + nt * 8 + (lane & 3) * 2;
#pragma unroll
            for (int h = 0; h < 2; h++) {
                int row = m0 + wm * 32 + mt * 16 + (lane >> 2) + 8 * h;
                float v0 = acc[mt][nt][2 * h + 0];
                float v1 = acc[mt][nt][2 * h + 1];
                if (MODE == 1) {
                    float2 lg, fc;
                    {
                        float z = fmaxf(v0, CL);
                        float w = fmaf(z, z, -1.0f);
                        float rs = rsqrtf(w);
                        float aa = __logf(fmaf(w, rs, z));
                        lg.x = -aa * aa;
                        fc.x = (v0 > CL) ? (-2.0f * aa * rs) : 0.0f;
                    }
                    {
                        float z = fmaxf(v1, CL);
                        float w = fmaf(z, z, -1.0f);
                        float rs = rsqrtf(w);
                        float aa = __logf(fmaf(w, rs, z));
                        lg.y = -aa * aa;
                        fc.y = (v1 > CL) ? (-2.0f * aa * rs) : 0.0f;
                    }
                    *(float2*)&g_logits[(size_t)row * NC + col] = lg;
                    *(float2*)&g_factor[(size_t)row * NC + col] = fc;
                } else {
                    float* out = g_gpart + (size_t)blockIdx.z * NC * NDIM2;
                    float2 gv; gv.x = v0; gv.y = v1;
                    *(float2*)&out[(size_t)row * NDIM2 + col] = gv;
                }
            }
        }
    }
}

// ================= elementwise chain =================
__global__ __launch_bounds__(256) void softmax_kernel() {
    __shared__ float red[256];
    const int i = blockIdx.x;
    const int t = threadIdx.x;
    const float* L = g_logits + (size_t)i * NC;

    float l[4];
    float mx = -1e30f;
#pragma unroll
    for (int e = 0; e < 4; e++) { l[e] = L[t + 256 * e]; mx = fmaxf(mx, l[e]); }
    red[t] = mx; __syncthreads();
    for (int s = 128; s > 0; s >>= 1) { if (t < s) red[t] = fmaxf(red[t], red[t + s]); __syncthreads(); }
    mx = red[0]; __syncthreads();

    float ex[4];
    float sm = 0.0f;
#pragma unroll
    for (int e = 0; e < 4; e++) { ex[e] = __expf(l[e] - mx); sm += ex[e]; }
    red[t] = sm; __syncthreads();
    for (int s = 128; s > 0; s >>= 1) { if (t < s) red[t] += red[t + s]; __syncthreads(); }
    float inv = 1.0f / red[0];

    float* P = g_P + (size_t)i * NC;
#pragma unroll
    for (int e = 0; e < 4; e++) P[t + 256 * e] = ex[e] * inv;
}

__global__ __launch_bounds__(256) void colpart_kernel() {
    const int j = blockIdx.x * 256 + threadIdx.x;
    const int i0 = blockIdx.y * 128;
    float s = 0.0f;
    for (int i = i0; i < i0 + 128; i++) s += g_P[(size_t)i * NC + j];
    g_colpart[blockIdx.y * NC + j] = s;
}

__global__ __launch_bounds__(256) void colreduce_kernel() {
    const int j = blockIdx.x * 256 + threadIdx.x;
    float s = 0.0f;
#pragma unroll
    for (int r = 0; r < 32; r++) s += g_colpart[r * NC + j];
    float pm = s * INVN;
    g_cm[j] = __logf(pm + EPS8) + pm / (pm + EPS8);
}

// A_i = -(1/N) * sum_j P_ij * (cm_j - l_ij)
__global__ __launch_bounds__(256) void rowdot_kernel() {
    __shared__ float scm[NC];
    __shared__ float red[256];
    const int i = blockIdx.x;
    const int t = threadIdx.x;
    const size_t base = (size_t)i * NC;
#pragma unroll
    for (int e = 0; e < 4; e++) scm[t + 256 * e] = g_cm[t + 256 * e];
    __syncthreads();
    float acc = 0.0f;
#pragma unroll
    for (int e = 0; e < 4; e++) {
        int j = t + 256 * e;
        acc += g_P[base + j] * (scm[j] - g_logits[base + j]);
    }
    red[t] = acc; __syncthreads();
    for (int s = 128; s > 0; s >>= 1) { if (t < s) red[t] += red[t + s]; __syncthreads(); }
    if (t == 0) g_Arow[i] = -red[0] * INVN;
}

// W_ij = P*((cm_j - l)*invN + A_i)*factor; write transposed bf16 split (Wh, Wl)
__global__ __launch_bounds__(256) void wgrad_t_kernel() {
    __shared__ float s[32][33];
    __shared__ float scm[32];
    const int i0 = blockIdx.x * 32;   // over NQ
    const int j0 = blockIdx.y * 32;   // over NC
    const int t = threadIdx.x;
    const int x = t & 31, y = t >> 5;
    if (t < 32) scm[t] = g_cm[j0 + t];
    __syncthreads();
    float cmv = scm[x];
#pragma unroll
    for (int r = 0; r < 4; r++) {
        int row = i0 + y + 8 * r;
        size_t idx = (size_t)row * NC + j0 + x;
        float pv = g_P[idx];
        float lv = g_logits[idx];
        float fv = g_factor[idx];
        float Av = g_Arow[row];
        s[x][y + 8 * r] = pv * (fmaf(cmv - lv, INVN, Av)) * fv;
    }
    __syncthreads();
#pragma unroll
    for (int w = t; w < 512; w += 256) {
        int jl = w >> 4, ip = w & 15;
        float v0 = s[jl][2 * ip], v1 = s[jl][2 * ip + 1];
        __nv_bfloat16 h0, l0, h1, l1;
        split2(v0, h0, l0); split2(v1, h1, l1);
        __nv_bfloat162 hh; hh.x = h0; hh.y = h1;
        __nv_bfloat162 ll; ll.x = l0; ll.y = l1;
        size_t base = (size_t)(j0 + jl) * KSEC + i0 + 2 * ip;
        *(__nv_bfloat162*)&g_Wt2[0][base] = hh;
        *(__nv_bfloat162*)&g_Wt2[1][base] = ll;
    }
}

// ================= AdamW + reproject =================
__global__ __launch_bounds__(256) void adam_kernel(float corr1, float corr2) {
    __shared__ float red[256];
    const int j = blockIdx.x;
    const int t = threadIdx.x;

    float ss = 0.0f;
#pragma unroll
    for (int e = 0; e < 2; e++) {
        int c = t + 256 * e;          // 0..511 -> d = c+1
        int idx = j * DP + c + 1;
        float g = 0.0f;
#pragma unroll
        for (int z = 0; z < 6; z++)
            g += g_gpart[(size_t)z * NC * NDIM2 + (size_t)j * NDIM2 + c];
        float m = 0.9f * g_m[idx] + 0.1f * g;
        float v = 0.999f * g_v[idx] + 0.001f * (g * g);
        g_m[idx] = m; g_v[idx] = v;
        float mh = m * corr1;
        float vh = v * corr2;
        float xx = g_protos[idx] * 0.999f - 0.1f * mh / (sqrtf(vh) + EPS8);
        g_protos[idx] = xx;
        ss += xx * xx;
    }
    red[t] = ss; __syncthreads();
    for (int sft = 128; sft > 0; sft >>= 1) { if (t < sft) red[t] += red[t + sft]; __syncthreads(); }
    if (t == 0) g_protos[j * DP] = sqrtf(1.0f + red[0]);
}

__global__ void pack_kernel(float* __restrict__ out) {
    int idx = blockIdx.x * blockDim.x + threadIdx.x;
    if (idx >= NC * DD) return;
    int i = idx / DD, d = idx % DD;
    out[idx] = g_protos[i * DP + d];
}

// ================= launch =================
extern "C" void kernel_launch(void* const* d_in, const int* in_sizes, int n_in,
                              void* d_out, int out_size) {
    const float* protos_in = (const float*)d_in[0];
    const float* query_in  = (const float*)d_in[1];
    (void)in_sizes; (void)n_in; (void)out_size;

    cudaFuncSetAttribute(mma_gemm<1>, cudaFuncAttributeMaxDynamicSharedMemorySize, SMEM_BYTES);
    cudaFuncSetAttribute(mma_gemm<2>, cudaFuncAttributeMaxDynamicSharedMemorySize, SMEM_BYTES);

    prep_q_kernel<<<(NQ * DP + 255) / 256, 256>>>(query_in);
    prep_q4_kernel<<<(NQ * K1 + 255) / 256, 256>>>();
    prep_qT2_kernel<<<(NDIM2 * NQ + 255) / 256, 256>>>();
    prep_p_kernel<<<(NC * DP + 255) / 256, 256>>>(protos_in);

    for (int t = 1; t <= NITER; t++) {
        split_p_kernel<<<(NC * K1 + 255) / 256, 256>>>();
        mma_gemm<1><<<dim3(NC / 128, NQ / 128), 256, SMEM_BYTES>>>();
        softmax_kernel<<<NQ, 256>>>();
        colpart_kernel<<<dim3(NC / 256, 32), 256>>>();
        colreduce_kernel<<<NC / 256, 256>>>();
        rowdot_kernel<<<NQ, 256>>>();
        wgrad_t_kernel<<<dim3(NQ / 32, NC / 32), 256>>>();
        mma_gemm<2><<<dim3(NDIM2 / 128, NC / 128, 6), 256, SMEM_BYTES>>>();
        double c1 = 1.0 / (1.0 - pow(0.9,   (double)t));
        double c2 = 1.0 / (1.0 - pow(0.999, (double)t));
        adam_kernel<<<NC, 256>>>((float)c1, (float)c2);
    }
    pack_kernel<<<(NC * DD + 255) / 256, 256>>>((float*)d_out);
}

// round 5
// speedup vs baseline: 2.9302x; 1.1430x over previous
#include <cuda_runtime.h>
#include <cuda_bf16.h>
#include <math.h>
#include <stdint.h>

#define NQ 4096
#define NC 1024
#define DD 513
#define DP 528            // fp32 padded dim
#define K1 2112           // 4 sections * 528
#define NDIM2 512         // gemm2 N (space coords 1..512)
#define KSEC 4096         // gemm2 per-section K
#define NSPLIT 12         // gemm2 split-K slices
#define NITER 20
#define EPS8 1e-8f
#define INVN (1.0f/4096.0f)

__device__ __forceinline__ uint32_t smem_u32(const void* p) {
    uint32_t a;
    asm("{ .reg .u64 t; cvta.to.shared.u64 t, %1; cvt.u32.u64 %0, t; }" : "=r"(a) : "l"(p));
    return a;
}

// ================= persistent buffers =================
__device__ float g_qhat  [NQ * DP];
__device__ float g_protos[NC * DP];
__device__ float g_logits[NQ * NC];
__device__ float g_factor[NQ * NC];
__device__ float g_P     [NQ * NC];
__device__ float g_cm    [NC];
__device__ float g_Arow  [NQ];
__device__ float g_colpart[32 * NC];
__device__ float g_m     [NC * DP];
__device__ float g_v     [NC * DP];
__device__ __nv_bfloat16 g_q4 [(size_t)NQ * K1];          // [qh|qh|ql|ql]
__device__ __nv_bfloat16 g_p4 [(size_t)NC * K1];          // [ph|pl|ph|pl]
__device__ __nv_bfloat16 g_qT2[2][(size_t)NDIM2 * KSEC];  // [qh^T], [ql^T]
__device__ __nv_bfloat16 g_Wt2[2][(size_t)NC * KSEC];     // [Wh^T], [Wl^T]
__device__ float g_gpart[NSPLIT * (size_t)NC * NDIM2];

__device__ __forceinline__ void split2(float v, __nv_bfloat16& hi, __nv_bfloat16& lo) {
    hi = __float2bfloat16(v);
    lo = __float2bfloat16(v - __bfloat162float(hi));
}

// ================= prep =================
__global__ void prep_q_kernel(const float* __restrict__ q) {
    int idx = blockIdx.x * blockDim.x + threadIdx.x;
    if (idx >= NQ * DP) return;
    int i = idx / DP, d = idx % DP;
    float v = 0.0f;
    if (d < DD) { v = q[i * DD + d]; if (d > 0) v = -v; }
    g_qhat[idx] = v;
}
__global__ void prep_q4_kernel() {
    int idx = blockIdx.x * blockDim.x + threadIdx.x;
    if (idx >= NQ * K1) return;
    int i = idx / K1, d = idx % K1;
    int sec = d / DP, dd = d % DP;
    float v = g_qhat[i * DP + dd];
    __nv_bfloat16 hi, lo; split2(v, hi, lo);
    g_q4[(size_t)i * K1 + d] = (sec < 2) ? hi : lo;
}
__global__ void prep_qT2_kernel() {
    int idx = blockIdx.x * blockDim.x + threadIdx.x;
    if (idx >= NDIM2 * NQ) return;
    int r = idx / NQ, i = idx % NQ;
    float v = g_qhat[i * DP + r + 1];
    __nv_bfloat16 hi, lo; split2(v, hi, lo);
    g_qT2[0][(size_t)r * KSEC + i] = hi;
    g_qT2[1][(size_t)r * KSEC + i] = lo;
}
__global__ void prep_p_kernel(const float* __restrict__ p) {
    int idx = blockIdx.x * blockDim.x + threadIdx.x;
    if (idx >= NC * DP) return;
    int i = idx / DP, d = idx % DP;
    float v = 0.0f;
    if (d < DD) v = p[i * DD + d];
    g_protos[idx] = v;
    g_m[idx] = 0.0f;
    g_v[idx] = 0.0f;
}
__global__ void split_p_kernel() {
    int idx = blockIdx.x * blockDim.x + threadIdx.x;
    if (idx >= NC * K1) return;
    int j = idx / K1, d = idx % K1;
    int sec = d / DP, dd = d % DP;
    float v = g_protos[j * DP + dd];
    __nv_bfloat16 hi, lo; split2(v, hi, lo);
    g_p4[(size_t)j * K1 + d] = (sec & 1) ? lo : hi;
}

// ================= mma.sync GEMM (3-stage cp.async pipeline) =================
// MODE 1: logits = q4 @ p4^T + acosh epilogue.  grid (8, 32). K=2112 (33 chunks)
// MODE 2: grad partials, 3 section-pairs x split-4.  grid (4, 8, 12). K=1024/CTA
#define SMEM_BYTES 98304

__device__ __forceinline__ void ld_x4(uint32_t* r, uint32_t addr) {
    asm volatile("ldmatrix.sync.aligned.m8n8.x4.shared.b16 {%0,%1,%2,%3}, [%4];"
        : "=r"(r[0]), "=r"(r[1]), "=r"(r[2]), "=r"(r[3]) : "r"(addr));
}
__device__ __forceinline__ void mma16816(float* d, const uint32_t* a, const uint32_t* b) {
    asm volatile("mma.sync.aligned.m16n8k16.row.col.f32.bf16.bf16.f32 "
        "{%0,%1,%2,%3}, {%4,%5,%6,%7}, {%8,%9}, {%0,%1,%2,%3};"
        : "+f"(d[0]), "+f"(d[1]), "+f"(d[2]), "+f"(d[3])
        : "r"(a[0]), "r"(a[1]), "r"(a[2]), "r"(a[3]), "r"(b[0]), "r"(b[1]));
}

__device__ __forceinline__ void load_stage(uint32_t sA, const char* Ab, const char* Bb,
                                           size_t kbytes, size_t gk, int tid) {
    uint32_t sB = sA + 16384;
#pragma unroll
    for (int t = 0; t < 4; t++) {
        int idx = tid + 256 * t;
        int r = idx >> 3, c = idx & 7;
        uint32_t sw = (uint32_t)(r * 128 + ((c ^ (r & 7)) << 4));
        const char* g = Ab + (size_t)r * kbytes + gk + c * 16;
        asm volatile("cp.async.cg.shared.global [%0], [%1], 16;" :: "r"(sA + sw), "l"(g));
    }
#pragma unroll
    for (int t = 0; t < 4; t++) {
        int idx = tid + 256 * t;
        int r = idx >> 3, c = idx & 7;
        uint32_t sw = (uint32_t)(r * 128 + ((c ^ (r & 7)) << 4));
        const char* g = Bb + (size_t)r * kbytes + gk + c * 16;
        asm volatile("cp.async.cg.shared.global [%0], [%1], 16;" :: "r"(sB + sw), "l"(g));
    }
    asm volatile("cp.async.commit_group;" ::: "memory");
}

template <int MODE>
__global__ __launch_bounds__(256, 2) void mma_gemm() {
    extern __shared__ char smem[];
    const uint32_t sb = smem_u32(smem);
    const int tid = threadIdx.x;
    const int warp = tid >> 5, lane = tid & 31;
    const int wm = warp & 3, wn = warp >> 2;

    const int m0 = blockIdx.y * 128;
    const int n0 = blockIdx.x * 128;
    const char* Abase;
    const char* Bbase;
    size_t kbytes, koff;
    int nch;
    if (MODE == 1) {
        Abase = (const char*)g_q4 + (size_t)m0 * K1 * 2;
        Bbase = (const char*)g_p4 + (size_t)n0 * K1 * 2;
        kbytes = (size_t)K1 * 2; nch = K1 / 64; koff = 0;
    } else {
        int z = blockIdx.z;
        int s = z >> 2, h = z & 3;          // s: section pair, h: K quarter
        int ai = (s == 2) ? 1 : 0;
        int bi = (s == 1) ? 1 : 0;
        Abase = (const char*)&g_Wt2[ai][0] + (size_t)m0 * KSEC * 2;
        Bbase = (const char*)&g_qT2[bi][0] + (size_t)n0 * KSEC * 2;
        kbytes = (size_t)KSEC * 2; nch = 1024 / 64;
        koff = (size_t)h * 1024 * 2;
    }

    load_stage(sb, Abase, Bbase, kbytes, koff, tid);
    load_stage(sb + 32768, Abase, Bbase, kbytes, koff + 128, tid);
    asm volatile("cp.async.wait_group 1;" ::: "memory");
    __syncthreads();

    float acc[2][8][4];
#pragma unroll
    for (int mt = 0; mt < 2; mt++)
#pragma unroll
        for (int nt = 0; nt < 8; nt++)
#pragma unroll
            for (int e = 0; e < 4; e++) acc[mt][nt][e] = 0.0f;

    for (int ch = 0; ch < nch; ch++) {
        const uint32_t sA = sb + (uint32_t)(ch % 3) * 32768;
        const uint32_t sB = sA + 16384;

#pragma unroll
        for (int kk = 0; kk < 4; kk++) {
            uint32_t a[2][4], b[8][2];
#pragma unroll
            for (int mt = 0; mt < 2; mt++) {
                int r = wm * 32 + mt * 16 + (lane & 15);
                int c = ((lane >> 4) + 2 * kk) ^ (r & 7);
                ld_x4(a[mt], sA + r * 128 + c * 16);
            }
#pragma unroll
            for (int np = 0; np < 4; np++) {
                int r = wn * 64 + np * 16 + (lane & 7) + ((lane >> 4) << 3);
                int c = (((lane >> 3) & 1) + 2 * kk) ^ (r & 7);
                uint32_t tmp[4];
                ld_x4(tmp, sB + r * 128 + c * 16);
                b[2 * np][0] = tmp[0]; b[2 * np][1] = tmp[1];
                b[2 * np + 1][0] = tmp[2]; b[2 * np + 1][1] = tmp[3];
            }
#pragma unroll
            for (int mt = 0; mt < 2; mt++)
#pragma unroll
                for (int nt = 0; nt < 8; nt++)
                    mma16816(acc[mt][nt], a[mt], b[nt]);
        }

        if (ch + 2 < nch) {
            load_stage(sb + (uint32_t)((ch + 2) % 3) * 32768, Abase, Bbase,
                       kbytes, koff + (size_t)(ch + 2) * 128, tid);
            asm volatile("cp.async.wait_group 1;" ::: "memory");
        } else {
            asm volatile("cp.async.wait_group 0;" ::: "memory");
        }
        __syncthreads();
    }

    // ---------------- epilogue ----------------
    const float CL = 1.0f + 1e-7f;
#pragma unroll
    for (int mt = 0; mt < 2; mt++) {
#pragma unroll
        for (int nt = 0; nt < 8; nt++) {
            int col = n0 + wn * 64 + nt * 8 + (lane & 3) * 2;
#pragma unroll
            for (int h = 0; h < 2; h++) {
                int row = m0 + wm * 32 + mt * 16 + (lane >> 2) + 8 * h;
                float v0 = acc[mt][nt][2 * h + 0];
                float v1 = acc[mt][nt][2 * h + 1];
                if (MODE == 1) {
                    float2 lg, fc;
                    {
                        float z = fmaxf(v0, CL);
                        float w = fmaf(z, z, -1.0f);
                        float rs = rsqrtf(w);
                        float aa = __logf(fmaf(w, rs, z));
                        lg.x = -aa * aa;
                        fc.x = (v0 > CL) ? (-2.0f * aa * rs) : 0.0f;
                    }
                    {
                        float z = fmaxf(v1, CL);
                        float w = fmaf(z, z, -1.0f);
                        float rs = rsqrtf(w);
                        float aa = __logf(fmaf(w, rs, z));
                        lg.y = -aa * aa;
                        fc.y = (v1 > CL) ? (-2.0f * aa * rs) : 0.0f;
                    }
                    *(float2*)&g_logits[(size_t)row * NC + col] = lg;
                    *(float2*)&g_factor[(size_t)row * NC + col] = fc;
                } else {
                    float* out = g_gpart + (size_t)blockIdx.z * NC * NDIM2;
                    float2 gv; gv.x = v0; gv.y = v1;
                    *(float2*)&out[(size_t)row * NDIM2 + col] = gv;
                }
            }
        }
    }
}

// ================= elementwise chain =================
// softmax without max-pass: logits = -a^2 in [-inf, 0], exp never overflows
// and row-max logit is >= -50ish, so the sum is far above fp32 denormal range.
__global__ __launch_bounds__(256) void softmax_kernel() {
    __shared__ float red[256];
    const int i = blockIdx.x;
    const int t = threadIdx.x;
    const float* L = g_logits + (size_t)i * NC;

    float ex[4];
    float sm = 0.0f;
#pragma unroll
    for (int e = 0; e < 4; e++) { ex[e] = __expf(L[t + 256 * e]); sm += ex[e]; }
    red[t] = sm; __syncthreads();
    for (int s = 128; s > 0; s >>= 1) { if (t < s) red[t] += red[t + s]; __syncthreads(); }
    float inv = 1.0f / red[0];

    float* P = g_P + (size_t)i * NC;
#pragma unroll
    for (int e = 0; e < 4; e++) P[t + 256 * e] = ex[e] * inv;
}

__global__ __launch_bounds__(256) void colpart_kernel() {
    const int j = blockIdx.x * 256 + threadIdx.x;
    const int i0 = blockIdx.y * 128;
    float s = 0.0f;
    for (int i = i0; i < i0 + 128; i++) s += g_P[(size_t)i * NC + j];
    g_colpart[blockIdx.y * NC + j] = s;
}

__global__ __launch_bounds__(256) void colreduce_kernel() {
    const int j = blockIdx.x * 256 + threadIdx.x;
    float s = 0.0f;
#pragma unroll
    for (int r = 0; r < 32; r++) s += g_colpart[r * NC + j];
    float pm = s * INVN;
    g_cm[j] = __logf(pm + EPS8) + pm / (pm + EPS8);
}

// A_i = -(1/N) * sum_j P_ij * (cm_j - l_ij)
__global__ __launch_bounds__(256) void rowdot_kernel() {
    __shared__ float scm[NC];
    __shared__ float red[256];
    const int i = blockIdx.x;
    const int t = threadIdx.x;
    const size_t base = (size_t)i * NC;
#pragma unroll
    for (int e = 0; e < 4; e++) scm[t + 256 * e] = g_cm[t + 256 * e];
    __syncthreads();
    float acc = 0.0f;
#pragma unroll
    for (int e = 0; e < 4; e++) {
        int j = t + 256 * e;
        acc += g_P[base + j] * (scm[j] - g_logits[base + j]);
    }
    red[t] = acc; __syncthreads();
    for (int s = 128; s > 0; s >>= 1) { if (t < s) red[t] += red[t + s]; __syncthreads(); }
    if (t == 0) g_Arow[i] = -red[0] * INVN;
}

// W_ij = P*((cm_j - l)*invN + A_i)*factor; write transposed bf16 split (Wh, Wl)
__global__ __launch_bounds__(256) void wgrad_t_kernel() {
    __shared__ float s[32][33];
    __shared__ float scm[32];
    const int i0 = blockIdx.x * 32;   // over NQ
    const int j0 = blockIdx.y * 32;   // over NC
    const int t = threadIdx.x;
    const int x = t & 31, y = t >> 5;
    if (t < 32) scm[t] = g_cm[j0 + t];
    __syncthreads();
    float cmv = scm[x];
#pragma unroll
    for (int r = 0; r < 4; r++) {
        int row = i0 + y + 8 * r;
        size_t idx = (size_t)row * NC + j0 + x;
        float pv = g_P[idx];
        float lv = g_logits[idx];
        float fv = g_factor[idx];
        float Av = g_Arow[row];
        s[x][y + 8 * r] = pv * (fmaf(cmv - lv, INVN, Av)) * fv;
    }
    __syncthreads();
#pragma unroll
    for (int w = t; w < 512; w += 256) {
        int jl = w >> 4, ip = w & 15;
        float v0 = s[jl][2 * ip], v1 = s[jl][2 * ip + 1];
        __nv_bfloat16 h0, l0, h1, l1;
        split2(v0, h0, l0); split2(v1, h1, l1);
        __nv_bfloat162 hh; hh.x = h0; hh.y = h1;
        __nv_bfloat162 ll; ll.x = l0; ll.y = l1;
        size_t base = (size_t)(j0 + jl) * KSEC + i0 + 2 * ip;
        *(__nv_bfloat162*)&g_Wt2[0][base] = hh;
        *(__nv_bfloat162*)&g_Wt2[1][base] = ll;
    }
}

// ================= AdamW + reproject + emit p4 split for next iter =================
__global__ __launch_bounds__(256) void adam_kernel(float corr1, float corr2) {
    __shared__ float red[256];
    const int j = blockIdx.x;
    const int t = threadIdx.x;
    const size_t p4base = (size_t)j * K1;

    float ss = 0.0f;
#pragma unroll
    for (int e = 0; e < 2; e++) {
        int c = t + 256 * e;          // 0..511 -> d = c+1
        int d = c + 1;
        int idx = j * DP + d;
        float g = 0.0f;
#pragma unroll
        for (int z = 0; z < NSPLIT; z++)
            g += g_gpart[(size_t)z * NC * NDIM2 + (size_t)j * NDIM2 + c];
        float m = 0.9f * g_m[idx] + 0.1f * g;
        float v = 0.999f * g_v[idx] + 0.001f * (g * g);
        g_m[idx] = m; g_v[idx] = v;
        float mh = m * corr1;
        float vh = v * corr2;
        float xx = g_protos[idx] * 0.999f - 0.1f * mh / (sqrtf(vh) + EPS8);
        g_protos[idx] = xx;
        __nv_bfloat16 hi, lo; split2(xx, hi, lo);
        g_p4[p4base + d] = hi;
        g_p4[p4base + DP + d] = lo;
        g_p4[p4base + 2 * DP + d] = hi;
        g_p4[p4base + 3 * DP + d] = lo;
        ss += xx * xx;
    }
    red[t] = ss; __syncthreads();
    for (int sft = 128; sft > 0; sft >>= 1) { if (t < sft) red[t] += red[t + sft]; __syncthreads(); }
    if (t == 0) {
        float tm = sqrtf(1.0f + red[0]);
        g_protos[j * DP] = tm;
        __nv_bfloat16 hi, lo; split2(tm, hi, lo);
        g_p4[p4base] = hi;
        g_p4[p4base + DP] = lo;
        g_p4[p4base + 2 * DP] = hi;
        g_p4[p4base + 3 * DP] = lo;
    }
}

__global__ void pack_kernel(float* __restrict__ out) {
    int idx = blockIdx.x * blockDim.x + threadIdx.x;
    if (idx >= NC * DD) return;
    int i = idx / DD, d = idx % DD;
    out[idx] = g_protos[i * DP + d];
}

// ================= launch =================
extern "C" void kernel_launch(void* const* d_in, const int* in_sizes, int n_in,
                              void* d_out, int out_size) {
    const float* protos_in = (const float*)d_in[0];
    const float* query_in  = (const float*)d_in[1];
    (void)in_sizes; (void)n_in; (void)out_size;

    cudaFuncSetAttribute(mma_gemm<1>, cudaFuncAttributeMaxDynamicSharedMemorySize, SMEM_BYTES);
    cudaFuncSetAttribute(mma_gemm<2>, cudaFuncAttributeMaxDynamicSharedMemorySize, SMEM_BYTES);

    prep_q_kernel<<<(NQ * DP + 255) / 256, 256>>>(query_in);
    prep_q4_kernel<<<(NQ * K1 + 255) / 256, 256>>>();
    prep_qT2_kernel<<<(NDIM2 * NQ + 255) / 256, 256>>>();
    prep_p_kernel<<<(NC * DP + 255) / 256, 256>>>(protos_in);
    split_p_kernel<<<(NC * K1 + 255) / 256, 256>>>();

    for (int t = 1; t <= NITER; t++) {
        mma_gemm<1><<<dim3(NC / 128, NQ / 128), 256, SMEM_BYTES>>>();
        softmax_kernel<<<NQ, 256>>>();
        colpart_kernel<<<dim3(NC / 256, 32), 256>>>();
        colreduce_kernel<<<NC / 256, 256>>>();
        rowdot_kernel<<<NQ, 256>>>();
        wgrad_t_kernel<<<dim3(NQ / 32, NC / 32), 256>>>();
        mma_gemm<2><<<dim3(NDIM2 / 128, NC / 128, NSPLIT), 256, SMEM_BYTES>>>();
        double c1 = 1.0 / (1.0 - pow(0.9,   (double)t));
        double c2 = 1.0 / (1.0 - pow(0.999, (double)t));
        adam_kernel<<<NC, 256>>>((float)c1, (float)c2);
    }
    pack_kernel<<<(NC * DD + 255) / 256, 256>>>((float*)d_out);
}